// round 1
// baseline (speedup 1.0000x reference)
#include <cuda_runtime.h>
#include <math.h>

// ---------------- problem constants ----------------
#define SQ   1024
#define HDM  2048
#define NHQ  32
#define NKVH 4
#define HDHD 128
#define NE   32
#define TOPK 8
#define IDIM 768
#define NPAIR (SQ*TOPK)   // 8192

// ---------------- device scratch (static, allocation-free) ----------------
__device__ float g_h1[SQ*HDM];
__device__ float g_q [SQ*NHQ*HDHD];
__device__ float g_k [SQ*NKVH*HDHD];
__device__ float g_v [SQ*NKVH*HDHD];
__device__ float g_scores[(long long)NHQ*SQ*SQ];
__device__ float g_attn[SQ*NHQ*HDHD];
__device__ float g_aproj[SQ*HDM];
__device__ float g_h [SQ*HDM];
__device__ float g_h2[SQ*HDM];
__device__ float g_logits[SQ*NE];
__device__ float g_tw[NPAIR];
__device__ int   g_te[NPAIR];
__device__ int   g_counts[NE];
__device__ int   g_offsets[NE];
__device__ int   g_cursor[NE];
__device__ int   g_btok[NPAIR];
__device__ int   g_ppos[NPAIR];
__device__ float g_gu [(long long)NPAIR*2*IDIM];
__device__ float g_act[(long long)NPAIR*IDIM];
__device__ float g_ybuf[(long long)NPAIR*HDM];

// ---------------- small kernels ----------------
__global__ void zero32_kernel(int* counts, int* cursor) {
    int i = threadIdx.x;
    if (i < NE) { counts[i] = 0; cursor[i] = 0; }
}

__global__ void rmsnorm_kernel(const float* __restrict__ x, const float* __restrict__ w,
                               float* __restrict__ o, int ncols) {
    int row = blockIdx.x;
    const float* xr = x + (long long)row * ncols;
    float* orow = o + (long long)row * ncols;
    __shared__ float red[256];
    float s = 0.f;
    for (int c = threadIdx.x; c < ncols; c += 256) { float t = xr[c]; s += t * t; }
    red[threadIdx.x] = s; __syncthreads();
    for (int st = 128; st > 0; st >>= 1) {
        if (threadIdx.x < st) red[threadIdx.x] += red[threadIdx.x + st];
        __syncthreads();
    }
    float rms = rsqrtf(red[0] / (float)ncols + 1e-6f);
    for (int c = threadIdx.x; c < ncols; c += 256) orow[c] = xr[c] * rms * w[c];
}

// per-head q/k RMSNorm + RoPE, 128 threads per (slot, token)
__global__ void qknorm_rope_kernel(float* __restrict__ q, float* __restrict__ k,
                                   const float* __restrict__ qw, const float* __restrict__ kw) {
    int slot = blockIdx.x;          // 0..31 q heads, 32..35 k heads
    int t    = blockIdx.y;
    float* vec; const float* w;
    if (slot < NHQ) { vec = q + (long long)t * (NHQ*HDHD) + slot * HDHD; w = qw; }
    else            { vec = k + (long long)t * (NKVH*HDHD) + (slot - NHQ) * HDHD; w = kw; }
    int d = threadIdx.x;
    float v = vec[d];
    float s = v * v;
    #pragma unroll
    for (int o = 16; o > 0; o >>= 1) s += __shfl_xor_sync(0xffffffffu, s, o);
    __shared__ float red[4];
    if ((d & 31) == 0) red[d >> 5] = s;
    __syncthreads();
    float tot = red[0] + red[1] + red[2] + red[3];
    float rms = rsqrtf(tot / 128.f + 1e-6f);
    float nv = v * rms * w[d];
    __shared__ float sv[128];
    sv[d] = nv;
    __syncthreads();
    int d2 = d & 63;
    float angle = (float)t * powf(10000.0f, -(float)(2 * d2) / 128.0f);
    float c = cosf(angle), sn = sinf(angle);
    float other = (d < 64) ? -sv[d + 64] : sv[d - 64];
    vec[d] = nv * c + other * sn;
}

// causal softmax in-place on scores[h][i][*]; zero-fill j>i
__global__ void softmax_kernel(float* __restrict__ scores) {
    int i = blockIdx.x, h = blockIdx.y;
    float* row = scores + ((long long)h * SQ + i) * SQ;
    int len = i + 1;
    __shared__ float red[256];
    float m = -1e30f;
    for (int j = threadIdx.x; j < len; j += 256) m = fmaxf(m, row[j]);
    red[threadIdx.x] = m; __syncthreads();
    for (int st = 128; st > 0; st >>= 1) {
        if (threadIdx.x < st) red[threadIdx.x] = fmaxf(red[threadIdx.x], red[threadIdx.x + st]);
        __syncthreads();
    }
    m = red[0]; __syncthreads();
    float s = 0.f;
    for (int j = threadIdx.x; j < len; j += 256) { float e = expf(row[j] - m); row[j] = e; s += e; }
    red[threadIdx.x] = s; __syncthreads();
    for (int st = 128; st > 0; st >>= 1) {
        if (threadIdx.x < st) red[threadIdx.x] += red[threadIdx.x + st];
        __syncthreads();
    }
    float inv = 1.f / red[0];
    for (int j = threadIdx.x; j < SQ; j += 256) row[j] = (j < len) ? row[j] * inv : 0.f;
}

__global__ void add_kernel(const float* __restrict__ a, const float* __restrict__ b,
                           float* __restrict__ o, int n) {
    int i = blockIdx.x * 256 + threadIdx.x;
    if (i < n) o[i] = a[i] + b[i];
}

// softmax over 32 experts + top-8 (strict > scan == lowest-index tie-break)
__global__ void topk_kernel(const float* __restrict__ logits, float* __restrict__ tw,
                            int* __restrict__ te) {
    int t = blockIdx.x * blockDim.x + threadIdx.x;
    if (t >= SQ) return;
    float p[NE];
    float m = -1e30f;
    for (int e = 0; e < NE; e++) { p[e] = logits[t * NE + e]; m = fmaxf(m, p[e]); }
    float s = 0.f;
    for (int e = 0; e < NE; e++) { p[e] = expf(p[e] - m); s += p[e]; }
    float inv = 1.f / s;
    bool used[NE];
    for (int e = 0; e < NE; e++) used[e] = false;
    for (int kk = 0; kk < TOPK; kk++) {
        int best = -1; float bv = -1e30f;
        for (int e = 0; e < NE; e++)
            if (!used[e] && p[e] > bv) { bv = p[e]; best = e; }
        used[best] = true;
        te[t * TOPK + kk] = best;
        tw[t * TOPK + kk] = p[best] * inv;
    }
}

__global__ void count_kernel(const int* __restrict__ te, int* __restrict__ counts) {
    int p = blockIdx.x * 256 + threadIdx.x;
    if (p < NPAIR) atomicAdd(&counts[te[p]], 1);
}

__global__ void scan_kernel(const int* __restrict__ counts, int* __restrict__ offsets) {
    if (threadIdx.x == 0) {
        int s = 0;
        for (int e = 0; e < NE; e++) { offsets[e] = s; s += counts[e]; }
    }
}

__global__ void assign_kernel(const int* __restrict__ te, const int* __restrict__ offsets,
                              int* __restrict__ cursor, int* __restrict__ btok,
                              int* __restrict__ ppos) {
    int p = blockIdx.x * 256 + threadIdx.x;
    if (p >= NPAIR) return;
    int e = te[p];
    int pos = offsets[e] + atomicAdd(&cursor[e], 1);
    btok[pos] = p >> 3;
    ppos[p] = pos;
}

__global__ void silu_kernel(const float* __restrict__ gu, float* __restrict__ act) {
    long long idx = (long long)blockIdx.x * 256 + threadIdx.x;
    if (idx >= (long long)NPAIR * IDIM) return;
    long long p = idx / IDIM, f = idx % IDIM;
    float g = gu[p * (2 * IDIM) + f];
    float u = gu[p * (2 * IDIM) + IDIM + f];
    act[idx] = (g / (1.f + expf(-g))) * u;
}

__global__ void combine_kernel(const float* __restrict__ h, const float* __restrict__ ybuf,
                               const int* __restrict__ ppos, const float* __restrict__ tw,
                               float* __restrict__ out) {
    int t = blockIdx.x;
    __shared__ int   pos[TOPK];
    __shared__ float ww[TOPK];
    if (threadIdx.x < TOPK) {
        pos[threadIdx.x] = ppos[t * TOPK + threadIdx.x];
        ww[threadIdx.x]  = tw[t * TOPK + threadIdx.x];
    }
    __syncthreads();
    for (int c = threadIdx.x; c < HDM; c += 256) {
        float acc = h[(long long)t * HDM + c];
        #pragma unroll
        for (int kk = 0; kk < TOPK; kk++)
            acc += ww[kk] * ybuf[(long long)pos[kk] * HDM + c];
        out[(long long)t * HDM + c] = acc;
    }
}

// ---------------- generic tiled GEMM (64x64x16, 256 thr, 4x4 per thread) ----------------
__global__ void gemm_kernel(const float* __restrict__ A, const float* __restrict__ B,
                            float* __restrict__ C,
                            int M, int N, int K, int lda, int ldb, int ldc,
                            long long sA, long long sB, long long sC,
                            int bDivB, int transB, float alpha) {
    int z = blockIdx.z;
    A += (long long)z * sA;
    B += (long long)(z / bDivB) * sB;
    C += (long long)z * sC;

    __shared__ float As[16][64 + 4];
    __shared__ float Bs[16][64];
    int tid = threadIdx.x;
    int tx = tid & 15, ty = tid >> 4;
    int row0 = blockIdx.y * 64;
    int col0 = blockIdx.x * 64;

    float acc[4][4] = {};
    for (int k0 = 0; k0 < K; k0 += 16) {
        for (int i = tid; i < 64 * 16; i += 256) {
            int m = i >> 4, kk = i & 15;
            int gr = row0 + m;
            As[kk][m] = (gr < M) ? A[(long long)gr * lda + k0 + kk] : 0.f;
        }
        for (int i = tid; i < 16 * 64; i += 256) {
            int kk = i >> 6, n = i & 63;
            int gc = col0 + n;
            float bv = 0.f;
            if (gc < N)
                bv = transB ? B[(long long)gc * ldb + (k0 + kk)]
                            : B[(long long)(k0 + kk) * ldb + gc];
            Bs[kk][n] = bv;
        }
        __syncthreads();
        #pragma unroll
        for (int kk = 0; kk < 16; kk++) {
            float a[4], b[4];
            #pragma unroll
            for (int i = 0; i < 4; i++) a[i] = As[kk][ty * 4 + i];
            #pragma unroll
            for (int j = 0; j < 4; j++) b[j] = Bs[kk][tx * 4 + j];
            #pragma unroll
            for (int i = 0; i < 4; i++)
                #pragma unroll
                for (int j = 0; j < 4; j++)
                    acc[i][j] += a[i] * b[j];
        }
        __syncthreads();
    }
    #pragma unroll
    for (int i = 0; i < 4; i++) {
        int r = row0 + ty * 4 + i;
        if (r >= M) continue;
        #pragma unroll
        for (int j = 0; j < 4; j++) {
            int c = col0 + tx * 4 + j;
            if (c < N) C[(long long)r * ldc + c] = alpha * acc[i][j];
        }
    }
}

// ---------------- MoE GEMM 1: gathered rows of h2 -> gu ----------------
__global__ void moe_gemm1_kernel(const float* __restrict__ h2, const float* __restrict__ Wgu,
                                 float* __restrict__ gu, const int* __restrict__ counts,
                                 const int* __restrict__ offsets, const int* __restrict__ btok) {
    int e = blockIdx.z;
    int cnt = counts[e];
    int row0 = blockIdx.y * 64;
    if (row0 >= cnt) return;
    int start = offsets[e];
    const float* B = Wgu + (long long)e * (HDM * 2 * IDIM);

    __shared__ float As[16][64 + 4];
    __shared__ float Bs[16][64];
    __shared__ int   toks[64];
    int tid = threadIdx.x;
    if (tid < 64) toks[tid] = (row0 + tid < cnt) ? btok[start + row0 + tid] : 0;
    __syncthreads();

    int tx = tid & 15, ty = tid >> 4;
    int col0 = blockIdx.x * 64;
    float acc[4][4] = {};
    for (int k0 = 0; k0 < HDM; k0 += 16) {
        for (int i = tid; i < 64 * 16; i += 256) {
            int m = i >> 4, kk = i & 15;
            As[kk][m] = (row0 + m < cnt) ? h2[(long long)toks[m] * HDM + k0 + kk] : 0.f;
        }
        for (int i = tid; i < 16 * 64; i += 256) {
            int kk = i >> 6, n = i & 63;
            Bs[kk][n] = B[(long long)(k0 + kk) * (2 * IDIM) + col0 + n];
        }
        __syncthreads();
        #pragma unroll
        for (int kk = 0; kk < 16; kk++) {
            float a[4], b[4];
            #pragma unroll
            for (int i = 0; i < 4; i++) a[i] = As[kk][ty * 4 + i];
            #pragma unroll
            for (int j = 0; j < 4; j++) b[j] = Bs[kk][tx * 4 + j];
            #pragma unroll
            for (int i = 0; i < 4; i++)
                #pragma unroll
                for (int j = 0; j < 4; j++)
                    acc[i][j] += a[i] * b[j];
        }
        __syncthreads();
    }
    #pragma unroll
    for (int i = 0; i < 4; i++) {
        int r = row0 + ty * 4 + i;
        if (r >= cnt) continue;
        #pragma unroll
        for (int j = 0; j < 4; j++)
            gu[(long long)(start + r) * (2 * IDIM) + col0 + tx * 4 + j] = acc[i][j];
    }
}

// ---------------- MoE GEMM 2: act rows -> ybuf ----------------
__global__ void moe_gemm2_kernel(const float* __restrict__ act, const float* __restrict__ Wd,
                                 float* __restrict__ ybuf, const int* __restrict__ counts,
                                 const int* __restrict__ offsets) {
    int e = blockIdx.z;
    int cnt = counts[e];
    int row0 = blockIdx.y * 64;
    if (row0 >= cnt) return;
    int start = offsets[e];
    const float* A = act + (long long)start * IDIM;
    const float* B = Wd + (long long)e * (IDIM * HDM);

    __shared__ float As[16][64 + 4];
    __shared__ float Bs[16][64];
    int tid = threadIdx.x;
    int tx = tid & 15, ty = tid >> 4;
    int col0 = blockIdx.x * 64;
    float acc[4][4] = {};
    for (int k0 = 0; k0 < IDIM; k0 += 16) {
        for (int i = tid; i < 64 * 16; i += 256) {
            int m = i >> 4, kk = i & 15;
            As[kk][m] = (row0 + m < cnt) ? A[(long long)(row0 + m) * IDIM + k0 + kk] : 0.f;
        }
        for (int i = tid; i < 16 * 64; i += 256) {
            int kk = i >> 6, n = i & 63;
            Bs[kk][n] = B[(long long)(k0 + kk) * HDM + col0 + n];
        }
        __syncthreads();
        #pragma unroll
        for (int kk = 0; kk < 16; kk++) {
            float a[4], b[4];
            #pragma unroll
            for (int i = 0; i < 4; i++) a[i] = As[kk][ty * 4 + i];
            #pragma unroll
            for (int j = 0; j < 4; j++) b[j] = Bs[kk][tx * 4 + j];
            #pragma unroll
            for (int i = 0; i < 4; i++)
                #pragma unroll
                for (int j = 0; j < 4; j++)
                    acc[i][j] += a[i] * b[j];
        }
        __syncthreads();
    }
    #pragma unroll
    for (int i = 0; i < 4; i++) {
        int r = row0 + ty * 4 + i;
        if (r >= cnt) continue;
        #pragma unroll
        for (int j = 0; j < 4; j++)
            ybuf[(long long)(start + r) * HDM + col0 + tx * 4 + j] = acc[i][j];
    }
}

// ---------------- host launcher ----------------
static void* symaddr(const void* s) { void* p = nullptr; cudaGetSymbolAddress(&p, s); return p; }

extern "C" void kernel_launch(void* const* d_in, const int* in_sizes, int n_in,
                              void* d_out, int out_size) {
    const float* x   = (const float*)d_in[0];
    const float* ln1 = (const float*)d_in[1];
    const float* ln2 = (const float*)d_in[2];
    const float* qnw = (const float*)d_in[3];
    const float* knw = (const float*)d_in[4];
    const float* Wq  = (const float*)d_in[5];
    const float* Wk  = (const float*)d_in[6];
    const float* Wv  = (const float*)d_in[7];
    const float* Wo  = (const float*)d_in[8];
    const float* Wg  = (const float*)d_in[9];
    const float* Wgu = (const float*)d_in[10];
    const float* Wd  = (const float*)d_in[11];
    float* out = (float*)d_out;

    float* h1   = (float*)symaddr(g_h1);
    float* q    = (float*)symaddr(g_q);
    float* k    = (float*)symaddr(g_k);
    float* v    = (float*)symaddr(g_v);
    float* sc   = (float*)symaddr(g_scores);
    float* attn = (float*)symaddr(g_attn);
    float* ap   = (float*)symaddr(g_aproj);
    float* h    = (float*)symaddr(g_h);
    float* h2   = (float*)symaddr(g_h2);
    float* lg   = (float*)symaddr(g_logits);
    float* tw   = (float*)symaddr(g_tw);
    int*   te   = (int*)symaddr(g_te);
    int*   cnts = (int*)symaddr(g_counts);
    int*   offs = (int*)symaddr(g_offsets);
    int*   cur  = (int*)symaddr(g_cursor);
    int*   btok = (int*)symaddr(g_btok);
    int*   ppos = (int*)symaddr(g_ppos);
    float* gu   = (float*)symaddr(g_gu);
    float* act  = (float*)symaddr(g_act);
    float* ybuf = (float*)symaddr(g_ybuf);

    const float scale = 0.08838834764831843f;   // 1/sqrt(128)

    zero32_kernel<<<1, 32>>>(cnts, cur);

    // attention
    rmsnorm_kernel<<<SQ, 256>>>(x, ln1, h1, HDM);
    gemm_kernel<<<dim3(64, 16, 1), 256>>>(h1, Wq, q, SQ, NHQ*HDHD, HDM, HDM, NHQ*HDHD, NHQ*HDHD, 0, 0, 0, 1, 0, 1.f);
    gemm_kernel<<<dim3(8, 16, 1), 256>>>(h1, Wk, k, SQ, NKVH*HDHD, HDM, HDM, NKVH*HDHD, NKVH*HDHD, 0, 0, 0, 1, 0, 1.f);
    gemm_kernel<<<dim3(8, 16, 1), 256>>>(h1, Wv, v, SQ, NKVH*HDHD, HDM, HDM, NKVH*HDHD, NKVH*HDHD, 0, 0, 0, 1, 0, 1.f);
    qknorm_rope_kernel<<<dim3(NHQ + NKVH, SQ), 128>>>(q, k, qnw, knw);
    gemm_kernel<<<dim3(16, 16, NHQ), 256>>>(q, k, sc, SQ, SQ, HDHD,
                                            NHQ*HDHD, NKVH*HDHD, SQ,
                                            HDHD, HDHD, (long long)SQ*SQ, 8, 1, scale);
    softmax_kernel<<<dim3(SQ, NHQ), 256>>>(sc);
    gemm_kernel<<<dim3(2, 16, NHQ), 256>>>(sc, v, attn, SQ, HDHD, SQ,
                                           SQ, NKVH*HDHD, NHQ*HDHD,
                                           (long long)SQ*SQ, HDHD, HDHD, 8, 0, 1.f);
    gemm_kernel<<<dim3(32, 16, 1), 256>>>(attn, Wo, ap, SQ, HDM, NHQ*HDHD, NHQ*HDHD, HDM, HDM, 0, 0, 0, 1, 0, 1.f);
    add_kernel<<<(SQ*HDM + 255) / 256, 256>>>(x, ap, h, SQ*HDM);

    // MoE
    rmsnorm_kernel<<<SQ, 256>>>(h, ln2, h2, HDM);
    gemm_kernel<<<dim3(1, 16, 1), 256>>>(h2, Wg, lg, SQ, NE, HDM, HDM, NE, NE, 0, 0, 0, 1, 0, 1.f);
    topk_kernel<<<4, 256>>>(lg, tw, te);
    count_kernel<<<(NPAIR + 255) / 256, 256>>>(te, cnts);
    scan_kernel<<<1, 32>>>(cnts, offs);
    assign_kernel<<<(NPAIR + 255) / 256, 256>>>(te, offs, cur, btok, ppos);
    moe_gemm1_kernel<<<dim3(2*IDIM/64, 16, NE), 256>>>(h2, Wgu, gu, cnts, offs, btok);
    silu_kernel<<<(int)(((long long)NPAIR*IDIM + 255) / 256), 256>>>(gu, act);
    moe_gemm2_kernel<<<dim3(HDM/64, 16, NE), 256>>>(act, Wd, ybuf, cnts, offs);
    combine_kernel<<<SQ, 256>>>(h, ybuf, ppos, tw, out);
}

// round 2
// speedup vs baseline: 2.3969x; 2.3969x over previous
#include <cuda_runtime.h>
#include <math.h>
#include <stdint.h>

// ---------------- problem constants ----------------
#define SQ   1024
#define HDM  2048
#define NHQ  32
#define NKVH 4
#define HDHD 128
#define NE   32
#define TOPK 8
#define IDIM 768
#define NPAIR (SQ*TOPK)   // 8192

// ---------------- device scratch (static, allocation-free) ----------------
__device__ float g_h1[SQ*HDM];
__device__ float g_q [SQ*NHQ*HDHD];
__device__ float g_k [SQ*NKVH*HDHD];
__device__ float g_v [SQ*NKVH*HDHD];
__device__ float g_scores[(long long)NHQ*SQ*SQ];
__device__ float g_attn[SQ*NHQ*HDHD];
__device__ float g_h [SQ*HDM];
__device__ float g_h2[SQ*HDM];
__device__ float g_logits[SQ*NE];
__device__ float g_tw[NPAIR];
__device__ int   g_te[NPAIR];
__device__ int   g_counts[NE];
__device__ int   g_offsets[NE];
__device__ int   g_cursor[NE];
__device__ int   g_btok[NPAIR];
__device__ int   g_ppos[NPAIR];
__device__ float g_gu [(long long)NPAIR*2*IDIM];
__device__ float g_act[(long long)NPAIR*IDIM];
__device__ float g_ybuf[(long long)NPAIR*HDM];

// ---------------- helpers ----------------
__device__ __forceinline__ float tf32r(float x) {
    uint32_t o;
    asm("cvt.rna.tf32.f32 %0, %1;" : "=r"(o) : "f"(x));
    return __uint_as_float(o);
}

// ---------------- small kernels ----------------
__global__ void zero32_kernel(int* counts, int* cursor) {
    int i = threadIdx.x;
    if (i < NE) { counts[i] = 0; cursor[i] = 0; }
}

__global__ void rmsnorm_kernel(const float* __restrict__ x, const float* __restrict__ w,
                               float* __restrict__ o, int ncols) {
    int row = blockIdx.x;
    const float* xr = x + (long long)row * ncols;
    float* orow = o + (long long)row * ncols;
    __shared__ float red[256];
    float s = 0.f;
    for (int c = threadIdx.x; c < ncols; c += 256) { float t = xr[c]; s += t * t; }
    red[threadIdx.x] = s; __syncthreads();
    for (int st = 128; st > 0; st >>= 1) {
        if (threadIdx.x < st) red[threadIdx.x] += red[threadIdx.x + st];
        __syncthreads();
    }
    float rms = rsqrtf(red[0] / (float)ncols + 1e-6f);
    for (int c = threadIdx.x; c < ncols; c += 256) orow[c] = xr[c] * rms * w[c];
}

__global__ void qknorm_rope_kernel(float* __restrict__ q, float* __restrict__ k,
                                   const float* __restrict__ qw, const float* __restrict__ kw) {
    int slot = blockIdx.x;
    int t    = blockIdx.y;
    float* vec; const float* w;
    if (slot < NHQ) { vec = q + (long long)t * (NHQ*HDHD) + slot * HDHD; w = qw; }
    else            { vec = k + (long long)t * (NKVH*HDHD) + (slot - NHQ) * HDHD; w = kw; }
    int d = threadIdx.x;
    float v = vec[d];
    float s = v * v;
    #pragma unroll
    for (int o = 16; o > 0; o >>= 1) s += __shfl_xor_sync(0xffffffffu, s, o);
    __shared__ float red[4];
    if ((d & 31) == 0) red[d >> 5] = s;
    __syncthreads();
    float tot = red[0] + red[1] + red[2] + red[3];
    float rms = rsqrtf(tot / 128.f + 1e-6f);
    float nv = v * rms * w[d];
    __shared__ float sv[128];
    sv[d] = nv;
    __syncthreads();
    int d2 = d & 63;
    float angle = (float)t * powf(10000.0f, -(float)(2 * d2) / 128.0f);
    float c = cosf(angle), sn = sinf(angle);
    float other = (d < 64) ? -sv[d + 64] : sv[d - 64];
    vec[d] = nv * c + other * sn;
}

__global__ void softmax_kernel(float* __restrict__ scores) {
    int i = blockIdx.x, h = blockIdx.y;
    float* row = scores + ((long long)h * SQ + i) * SQ;
    int len = i + 1;
    __shared__ float red[256];
    float m = -1e30f;
    for (int j = threadIdx.x; j < len; j += 256) m = fmaxf(m, row[j]);
    red[threadIdx.x] = m; __syncthreads();
    for (int st = 128; st > 0; st >>= 1) {
        if (threadIdx.x < st) red[threadIdx.x] = fmaxf(red[threadIdx.x], red[threadIdx.x + st]);
        __syncthreads();
    }
    m = red[0]; __syncthreads();
    float s = 0.f;
    for (int j = threadIdx.x; j < len; j += 256) { float e = expf(row[j] - m); row[j] = e; s += e; }
    red[threadIdx.x] = s; __syncthreads();
    for (int st = 128; st > 0; st >>= 1) {
        if (threadIdx.x < st) red[threadIdx.x] += red[threadIdx.x + st];
        __syncthreads();
    }
    float inv = 1.f / red[0];
    for (int j = threadIdx.x; j < SQ; j += 256) row[j] = (j < len) ? row[j] * inv : 0.f;
}

__global__ void topk_kernel(const float* __restrict__ logits, float* __restrict__ tw,
                            int* __restrict__ te) {
    int t = blockIdx.x * blockDim.x + threadIdx.x;
    if (t >= SQ) return;
    float p[NE];
    float m = -1e30f;
    for (int e = 0; e < NE; e++) { p[e] = logits[t * NE + e]; m = fmaxf(m, p[e]); }
    float s = 0.f;
    for (int e = 0; e < NE; e++) { p[e] = expf(p[e] - m); s += p[e]; }
    float inv = 1.f / s;
    bool used[NE];
    for (int e = 0; e < NE; e++) used[e] = false;
    for (int kk = 0; kk < TOPK; kk++) {
        int best = -1; float bv = -1e30f;
        for (int e = 0; e < NE; e++)
            if (!used[e] && p[e] > bv) { bv = p[e]; best = e; }
        used[best] = true;
        te[t * TOPK + kk] = best;
        tw[t * TOPK + kk] = p[best] * inv;
    }
}

__global__ void count_kernel(const int* __restrict__ te, int* __restrict__ counts) {
    int p = blockIdx.x * 256 + threadIdx.x;
    if (p < NPAIR) atomicAdd(&counts[te[p]], 1);
}

__global__ void scan_kernel(const int* __restrict__ counts, int* __restrict__ offsets) {
    if (threadIdx.x == 0) {
        int s = 0;
        for (int e = 0; e < NE; e++) { offsets[e] = s; s += counts[e]; }
    }
}

__global__ void assign_kernel(const int* __restrict__ te, const int* __restrict__ offsets,
                              int* __restrict__ cursor, int* __restrict__ btok,
                              int* __restrict__ ppos) {
    int p = blockIdx.x * 256 + threadIdx.x;
    if (p >= NPAIR) return;
    int e = te[p];
    int pos = offsets[e] + atomicAdd(&cursor[e], 1);
    btok[pos] = p >> 3;
    ppos[p] = pos;
}

__global__ void silu_kernel(const float* __restrict__ gu, float* __restrict__ act) {
    long long idx = (long long)blockIdx.x * 256 + threadIdx.x;
    if (idx >= (long long)NPAIR * IDIM) return;
    long long p = idx / IDIM, f = idx % IDIM;
    float g = gu[p * (2 * IDIM) + f];
    float u = gu[p * (2 * IDIM) + IDIM + f];
    act[idx] = (g / (1.f + expf(-g))) * u;
}

__global__ void combine_kernel(const float* __restrict__ h, const float* __restrict__ ybuf,
                               const int* __restrict__ ppos, const float* __restrict__ tw,
                               float* __restrict__ out) {
    int t = blockIdx.x;
    __shared__ int   pos[TOPK];
    __shared__ float ww[TOPK];
    if (threadIdx.x < TOPK) {
        pos[threadIdx.x] = ppos[t * TOPK + threadIdx.x];
        ww[threadIdx.x]  = tw[t * TOPK + threadIdx.x];
    }
    __syncthreads();
    for (int c = threadIdx.x; c < HDM; c += 256) {
        float acc = h[(long long)t * HDM + c];
        #pragma unroll
        for (int kk = 0; kk < TOPK; kk++)
            acc += ww[kk] * ybuf[(long long)pos[kk] * HDM + c];
        out[(long long)t * HDM + c] = acc;
    }
}

// ---------------- exact fp32 SIMT GEMM (gate logits only — keeps top-k selection exact) ----
__global__ void gemm_simt_kernel(const float* __restrict__ A, const float* __restrict__ B,
                                 float* __restrict__ C, int M, int N, int K,
                                 int lda, int ldb, int ldc) {
    __shared__ float As[16][64 + 4];
    __shared__ float Bs[16][64];
    int tid = threadIdx.x;
    int tx = tid & 15, ty = tid >> 4;
    int row0 = blockIdx.y * 64;
    int col0 = blockIdx.x * 64;
    float acc[4][4] = {};
    for (int k0 = 0; k0 < K; k0 += 16) {
        for (int i = tid; i < 64 * 16; i += 256) {
            int m = i >> 4, kk = i & 15;
            int gr = row0 + m;
            As[kk][m] = (gr < M) ? A[(long long)gr * lda + k0 + kk] : 0.f;
        }
        for (int i = tid; i < 16 * 64; i += 256) {
            int kk = i >> 6, n = i & 63;
            int gc = col0 + n;
            Bs[kk][n] = (gc < N) ? B[(long long)(k0 + kk) * ldb + gc] : 0.f;
        }
        __syncthreads();
        #pragma unroll
        for (int kk = 0; kk < 16; kk++) {
            float a[4], b[4];
            #pragma unroll
            for (int i = 0; i < 4; i++) a[i] = As[kk][ty * 4 + i];
            #pragma unroll
            for (int j = 0; j < 4; j++) b[j] = Bs[kk][tx * 4 + j];
            #pragma unroll
            for (int i = 0; i < 4; i++)
                #pragma unroll
                for (int j = 0; j < 4; j++)
                    acc[i][j] += a[i] * b[j];
        }
        __syncthreads();
    }
    #pragma unroll
    for (int i = 0; i < 4; i++) {
        int r = row0 + ty * 4 + i;
        if (r >= M) continue;
        #pragma unroll
        for (int j = 0; j < 4; j++) {
            int c = col0 + tx * 4 + j;
            if (c < N) C[(long long)r * ldc + c] = acc[i][j];
        }
    }
}

// ---------------- tf32 tensor-core GEMM ----------------
// modes: 0 = normal batched (z via sA/sB/sC, bDivB)
//        1 = gathered-A rows via btok (MoE up/gate), z = expert
//        2 = contiguous rows from offsets[z] (MoE down), z = expert
template<int BM, int BN>
__global__ void __launch_bounds__(256)
gemm_tc(const float* __restrict__ A, const float* __restrict__ B, float* __restrict__ C,
        const float* __restrict__ resid,
        int M, int N, int K, int lda, int ldb, int ldc,
        long long sA, long long sB, long long sC, int bDivB,
        int transB, int causal, float alpha, int mode,
        const int* __restrict__ counts, const int* __restrict__ offsets,
        const int* __restrict__ btok) {
    constexpr int WM = BM / 2, WN = BN / 4;
    constexpr int FM = WM / 16, FN = WN / 8;

    int z = blockIdx.z;
    const float* Az = (mode == 0) ? (A + (long long)z * sA) : A;
    const float* Bz = (mode == 0) ? (B + (long long)(z / bDivB) * sB)
                                  : (B + (long long)z * sB);
    float* Cz = (mode == 0) ? (C + (long long)z * sC) : C;

    int cnt = M, start = 0;
    if (mode) { cnt = counts[z]; start = offsets[z]; }

    int row0 = blockIdx.y * BM, col0 = blockIdx.x * BN;
    if (mode && row0 >= cnt) return;
    if (causal && col0 > row0) return;

    __shared__ float As[16][BM + 4];
    __shared__ float Bs[16][BN + 4];
    __shared__ int stok[BM];

    int tid = threadIdx.x;
    if (mode == 1) {
        for (int i = tid; i < BM; i += 256)
            stok[i] = (row0 + i < cnt) ? btok[start + row0 + i] : 0;
        __syncthreads();
    }

    int warp = tid >> 5, lane = tid & 31;
    int wr = (warp >> 2) * WM, wc = (warp & 3) * WN;
    int g = lane >> 2, t = lane & 3;

    float acc[FM][FN][4];
    #pragma unroll
    for (int i = 0; i < FM; i++)
        #pragma unroll
        for (int j = 0; j < FN; j++)
            #pragma unroll
            for (int r = 0; r < 4; r++) acc[i][j][r] = 0.f;

    for (int k0 = 0; k0 < K; k0 += 16) {
        // ---- load A tile [BM x 16] ----
        #pragma unroll
        for (int i = tid; i < BM * 4; i += 256) {
            int r = i >> 2, kq = i & 3;
            float4 v = make_float4(0.f, 0.f, 0.f, 0.f);
            if (row0 + r < cnt) {
                long long ar;
                if (mode == 1)      ar = stok[r];
                else if (mode == 2) ar = start + row0 + r;
                else                ar = row0 + r;
                v = *reinterpret_cast<const float4*>(Az + ar * lda + k0 + kq * 4);
            }
            int kk = kq * 4;
            As[kk + 0][r] = tf32r(v.x);
            As[kk + 1][r] = tf32r(v.y);
            As[kk + 2][r] = tf32r(v.z);
            As[kk + 3][r] = tf32r(v.w);
        }
        // ---- load B tile -> Bs[k][n] ----
        if (!transB) {
            #pragma unroll
            for (int i = tid; i < 4 * BN; i += 256) {
                int kk = i / (BN / 4), nq = i % (BN / 4);
                float4 v = *reinterpret_cast<const float4*>(
                    Bz + (long long)(k0 + kk) * ldb + col0 + nq * 4);
                Bs[kk][nq * 4 + 0] = tf32r(v.x);
                Bs[kk][nq * 4 + 1] = tf32r(v.y);
                Bs[kk][nq * 4 + 2] = tf32r(v.z);
                Bs[kk][nq * 4 + 3] = tf32r(v.w);
            }
        } else {
            #pragma unroll
            for (int i = tid; i < BN * 4; i += 256) {
                int n = i >> 2, kq = i & 3;
                float4 v = *reinterpret_cast<const float4*>(
                    Bz + (long long)(col0 + n) * ldb + k0 + kq * 4);
                Bs[kq * 4 + 0][n] = tf32r(v.x);
                Bs[kq * 4 + 1][n] = tf32r(v.y);
                Bs[kq * 4 + 2][n] = tf32r(v.z);
                Bs[kq * 4 + 3][n] = tf32r(v.w);
            }
        }
        __syncthreads();

        // ---- 2 x m16n8k8 along k ----
        #pragma unroll
        for (int ks = 0; ks < 2; ks++) {
            int kb = ks * 8;
            uint32_t a[FM][4], b[FN][2];
            #pragma unroll
            for (int fm = 0; fm < FM; fm++) {
                int m0 = wr + fm * 16;
                a[fm][0] = __float_as_uint(As[kb + t][m0 + g]);
                a[fm][1] = __float_as_uint(As[kb + t][m0 + g + 8]);
                a[fm][2] = __float_as_uint(As[kb + t + 4][m0 + g]);
                a[fm][3] = __float_as_uint(As[kb + t + 4][m0 + g + 8]);
            }
            #pragma unroll
            for (int fn = 0; fn < FN; fn++) {
                int n0 = wc + fn * 8 + g;
                b[fn][0] = __float_as_uint(Bs[kb + t][n0]);
                b[fn][1] = __float_as_uint(Bs[kb + t + 4][n0]);
            }
            #pragma unroll
            for (int fm = 0; fm < FM; fm++)
                #pragma unroll
                for (int fn = 0; fn < FN; fn++) {
                    asm volatile(
                        "mma.sync.aligned.m16n8k8.row.col.f32.tf32.tf32.f32 "
                        "{%0,%1,%2,%3}, {%4,%5,%6,%7}, {%8,%9}, {%0,%1,%2,%3};"
                        : "+f"(acc[fm][fn][0]), "+f"(acc[fm][fn][1]),
                          "+f"(acc[fm][fn][2]), "+f"(acc[fm][fn][3])
                        : "r"(a[fm][0]), "r"(a[fm][1]), "r"(a[fm][2]), "r"(a[fm][3]),
                          "r"(b[fn][0]), "r"(b[fn][1]));
                }
        }
        __syncthreads();
    }

    // ---- epilogue ----
    #pragma unroll
    for (int fm = 0; fm < FM; fm++) {
        #pragma unroll
        for (int rr = 0; rr < 2; rr++) {
            int lr = wr + fm * 16 + g + rr * 8;
            if (row0 + lr >= cnt) continue;
            long long crow = (mode == 0) ? (long long)(row0 + lr)
                                         : (long long)(start + row0 + lr);
            float* cp = Cz + crow * ldc;
            const float* rp = resid ? (resid + (long long)(row0 + lr) * ldc) : nullptr;
            #pragma unroll
            for (int fn = 0; fn < FN; fn++) {
                int c = col0 + wc + fn * 8 + t * 2;
                float v0 = alpha * acc[fm][fn][rr * 2 + 0];
                float v1 = alpha * acc[fm][fn][rr * 2 + 1];
                if (rp) { v0 += rp[c]; v1 += rp[c + 1]; }
                cp[c] = v0;
                cp[c + 1] = v1;
            }
        }
    }
}

// ---------------- host launcher ----------------
static void* symaddr(const void* s) { void* p = nullptr; cudaGetSymbolAddress(&p, s); return p; }

extern "C" void kernel_launch(void* const* d_in, const int* in_sizes, int n_in,
                              void* d_out, int out_size) {
    const float* x   = (const float*)d_in[0];
    const float* ln1 = (const float*)d_in[1];
    const float* ln2 = (const float*)d_in[2];
    const float* qnw = (const float*)d_in[3];
    const float* knw = (const float*)d_in[4];
    const float* Wq  = (const float*)d_in[5];
    const float* Wk  = (const float*)d_in[6];
    const float* Wv  = (const float*)d_in[7];
    const float* Wo  = (const float*)d_in[8];
    const float* Wg  = (const float*)d_in[9];
    const float* Wgu = (const float*)d_in[10];
    const float* Wd  = (const float*)d_in[11];
    float* out = (float*)d_out;

    float* h1   = (float*)symaddr(g_h1);
    float* q    = (float*)symaddr(g_q);
    float* k    = (float*)symaddr(g_k);
    float* v    = (float*)symaddr(g_v);
    float* sc   = (float*)symaddr(g_scores);
    float* attn = (float*)symaddr(g_attn);
    float* h    = (float*)symaddr(g_h);
    float* h2   = (float*)symaddr(g_h2);
    float* lg   = (float*)symaddr(g_logits);
    float* tw   = (float*)symaddr(g_tw);
    int*   te   = (int*)symaddr(g_te);
    int*   cnts = (int*)symaddr(g_counts);
    int*   offs = (int*)symaddr(g_offsets);
    int*   cur  = (int*)symaddr(g_cursor);
    int*   btok = (int*)symaddr(g_btok);
    int*   ppos = (int*)symaddr(g_ppos);
    float* gu   = (float*)symaddr(g_gu);
    float* act  = (float*)symaddr(g_act);
    float* ybuf = (float*)symaddr(g_ybuf);

    const float scale = 0.08838834764831843f;   // 1/sqrt(128)

    zero32_kernel<<<1, 32>>>(cnts, cur);

    // ---- attention ----
    rmsnorm_kernel<<<SQ, 256>>>(x, ln1, h1, HDM);

    // Q proj: [1024,2048] @ [2048,4096]
    gemm_tc<128,128><<<dim3(32, 8, 1), 256>>>(h1, Wq, q, nullptr,
        SQ, NHQ*HDHD, HDM, HDM, NHQ*HDHD, NHQ*HDHD,
        0, 0, 0, 1, 0, 0, 1.f, 0, nullptr, nullptr, nullptr);
    // K/V proj: [1024,2048] @ [2048,512]
    gemm_tc<64,64><<<dim3(8, 16, 1), 256>>>(h1, Wk, k, nullptr,
        SQ, NKVH*HDHD, HDM, HDM, NKVH*HDHD, NKVH*HDHD,
        0, 0, 0, 1, 0, 0, 1.f, 0, nullptr, nullptr, nullptr);
    gemm_tc<64,64><<<dim3(8, 16, 1), 256>>>(h1, Wv, v, nullptr,
        SQ, NKVH*HDHD, HDM, HDM, NKVH*HDHD, NKVH*HDHD,
        0, 0, 0, 1, 0, 0, 1.f, 0, nullptr, nullptr, nullptr);

    qknorm_rope_kernel<<<dim3(NHQ + NKVH, SQ), 128>>>(q, k, qnw, knw);

    // scores = q @ k^T (causal: skip upper blocks)
    gemm_tc<128,128><<<dim3(8, 8, NHQ), 256>>>(q, k, sc, nullptr,
        SQ, SQ, HDHD, NHQ*HDHD, NKVH*HDHD, SQ,
        HDHD, HDHD, (long long)SQ*SQ, 8, 1, 1, scale, 0, nullptr, nullptr, nullptr);

    softmax_kernel<<<dim3(SQ, NHQ), 256>>>(sc);

    // attn = probs @ v
    gemm_tc<128,128><<<dim3(1, 8, NHQ), 256>>>(sc, v, attn, nullptr,
        SQ, HDHD, SQ, SQ, NKVH*HDHD, NHQ*HDHD,
        (long long)SQ*SQ, HDHD, HDHD, 8, 0, 0, 1.f, 0, nullptr, nullptr, nullptr);

    // h = x + attn @ Wo   (residual fused)
    gemm_tc<128,128><<<dim3(16, 8, 1), 256>>>(attn, Wo, h, x,
        SQ, HDM, NHQ*HDHD, NHQ*HDHD, HDM, HDM,
        0, 0, 0, 1, 0, 0, 1.f, 0, nullptr, nullptr, nullptr);

    // ---- MoE ----
    rmsnorm_kernel<<<SQ, 256>>>(h, ln2, h2, HDM);

    // gate logits: exact fp32 so top-k selection matches reference
    gemm_simt_kernel<<<dim3(1, 16, 1), 256>>>(h2, Wg, lg, SQ, NE, HDM, HDM, NE, NE);
    topk_kernel<<<4, 256>>>(lg, tw, te);
    count_kernel<<<(NPAIR + 255) / 256, 256>>>(te, cnts);
    scan_kernel<<<1, 32>>>(cnts, offs);
    assign_kernel<<<(NPAIR + 255) / 256, 256>>>(te, offs, cur, btok, ppos);

    // MoE up/gate: gathered rows of h2 -> gu
    gemm_tc<128,128><<<dim3(2*IDIM/128, 8, NE), 256>>>(h2, Wgu, gu, nullptr,
        SQ, 2*IDIM, HDM, HDM, 2*IDIM, 2*IDIM,
        0, (long long)HDM*2*IDIM, 0, 1, 0, 0, 1.f, 1, cnts, offs, btok);

    silu_kernel<<<(int)(((long long)NPAIR*IDIM + 255) / 256), 256>>>(gu, act);

    // MoE down: act rows -> ybuf
    gemm_tc<128,128><<<dim3(HDM/128, 8, NE), 256>>>(act, Wd, ybuf, nullptr,
        SQ, HDM, IDIM, IDIM, HDM, HDM,
        0, (long long)IDIM*HDM, 0, 1, 0, 0, 1.f, 2, cnts, offs, nullptr);

    combine_kernel<<<SQ, 256>>>(h, ybuf, ppos, tw, out);
}

// round 3
// speedup vs baseline: 3.7395x; 1.5602x over previous
#include <cuda_runtime.h>
#include <math.h>
#include <stdint.h>

// ---------------- problem constants ----------------
#define SQ   1024
#define HDM  2048
#define NHQ  32
#define NKVH 4
#define HDHD 128
#define NE   32
#define TOPK 8
#define IDIM 768
#define NPAIR (SQ*TOPK)   // 8192

// ---------------- device scratch ----------------
__device__ float g_h1[SQ*HDM];
__device__ float g_q [SQ*NHQ*HDHD];
__device__ float g_k [SQ*NKVH*HDHD];
__device__ float g_v [SQ*NKVH*HDHD];
__device__ float g_scores[(long long)NHQ*SQ*SQ];
__device__ float g_attn[SQ*NHQ*HDHD];
__device__ float g_h [SQ*HDM];
__device__ float g_h2[SQ*HDM];
__device__ float g_logits[SQ*NE];
__device__ float g_tw[NPAIR];
__device__ int   g_te[NPAIR];
__device__ int   g_counts[NE];
__device__ int   g_offsets[NE];
__device__ int   g_cursor[NE];
__device__ int   g_btok[NPAIR];
__device__ int   g_ppos[NPAIR];
__device__ float g_gu [(long long)NPAIR*2*IDIM];
__device__ float g_act[(long long)NPAIR*IDIM];
__device__ float g_ybuf[(long long)NPAIR*HDM];

// ---------------- cp.async helper ----------------
__device__ __forceinline__ void cpasync16(void* dst, const void* src, int srcsize) {
    uint32_t d = (uint32_t)__cvta_generic_to_shared(dst);
    asm volatile("cp.async.cg.shared.global [%0], [%1], 16, %2;"
                 :: "r"(d), "l"(src), "r"(srcsize) : "memory");
}
__device__ __forceinline__ void cpasync_commit() {
    asm volatile("cp.async.commit_group;" ::: "memory");
}

// ---------------- small kernels ----------------
__global__ void zero32_kernel(int* counts, int* cursor) {
    int i = threadIdx.x;
    if (i < NE) { counts[i] = 0; cursor[i] = 0; }
}

__global__ void rmsnorm_kernel(const float* __restrict__ x, const float* __restrict__ w,
                               float* __restrict__ o, int ncols) {
    int row = blockIdx.x;
    const float* xr = x + (long long)row * ncols;
    float* orow = o + (long long)row * ncols;
    __shared__ float red[256];
    float s = 0.f;
    for (int c = threadIdx.x; c < ncols; c += 256) { float t = xr[c]; s += t * t; }
    red[threadIdx.x] = s; __syncthreads();
    for (int st = 128; st > 0; st >>= 1) {
        if (threadIdx.x < st) red[threadIdx.x] += red[threadIdx.x + st];
        __syncthreads();
    }
    float rms = rsqrtf(red[0] / (float)ncols + 1e-6f);
    for (int c = threadIdx.x; c < ncols; c += 256) orow[c] = xr[c] * rms * w[c];
}

__global__ void qknorm_rope_kernel(float* __restrict__ q, float* __restrict__ k,
                                   const float* __restrict__ qw, const float* __restrict__ kw) {
    int slot = blockIdx.x;
    int t    = blockIdx.y;
    float* vec; const float* w;
    if (slot < NHQ) { vec = q + (long long)t * (NHQ*HDHD) + slot * HDHD; w = qw; }
    else            { vec = k + (long long)t * (NKVH*HDHD) + (slot - NHQ) * HDHD; w = kw; }
    int d = threadIdx.x;
    float v = vec[d];
    float s = v * v;
    #pragma unroll
    for (int o = 16; o > 0; o >>= 1) s += __shfl_xor_sync(0xffffffffu, s, o);
    __shared__ float red[4];
    if ((d & 31) == 0) red[d >> 5] = s;
    __syncthreads();
    float tot = red[0] + red[1] + red[2] + red[3];
    float rms = rsqrtf(tot / 128.f + 1e-6f);
    float nv = v * rms * w[d];
    __shared__ float sv[128];
    sv[d] = nv;
    __syncthreads();
    int d2 = d & 63;
    float angle = (float)t * powf(10000.0f, -(float)(2 * d2) / 128.0f);
    float c = cosf(angle), sn = sinf(angle);
    float other = (d < 64) ? -sv[d + 64] : sv[d - 64];
    vec[d] = nv * c + other * sn;
}

__global__ void softmax_kernel(float* __restrict__ scores) {
    int i = blockIdx.x, h = blockIdx.y;
    float* row = scores + ((long long)h * SQ + i) * SQ;
    int len = i + 1;
    __shared__ float red[256];
    float m = -1e30f;
    for (int j = threadIdx.x; j < len; j += 256) m = fmaxf(m, row[j]);
    red[threadIdx.x] = m; __syncthreads();
    for (int st = 128; st > 0; st >>= 1) {
        if (threadIdx.x < st) red[threadIdx.x] = fmaxf(red[threadIdx.x], red[threadIdx.x + st]);
        __syncthreads();
    }
    m = red[0]; __syncthreads();
    float s = 0.f;
    for (int j = threadIdx.x; j < len; j += 256) { float e = expf(row[j] - m); row[j] = e; s += e; }
    red[threadIdx.x] = s; __syncthreads();
    for (int st = 128; st > 0; st >>= 1) {
        if (threadIdx.x < st) red[threadIdx.x] += red[threadIdx.x + st];
        __syncthreads();
    }
    float inv = 1.f / red[0];
    // zero-fill up to next multiple of 128 past the diagonal (AV K-loop is trimmed)
    int fill = ((i >> 7) + 1) << 7;
    for (int j = threadIdx.x; j < fill; j += 256) row[j] = (j < len) ? row[j] * inv : 0.f;
}

__global__ void topk_kernel(const float* __restrict__ logits, float* __restrict__ tw,
                            int* __restrict__ te) {
    int t = blockIdx.x * blockDim.x + threadIdx.x;
    if (t >= SQ) return;
    float p[NE];
    float m = -1e30f;
    for (int e = 0; e < NE; e++) { p[e] = logits[t * NE + e]; m = fmaxf(m, p[e]); }
    float s = 0.f;
    for (int e = 0; e < NE; e++) { p[e] = expf(p[e] - m); s += p[e]; }
    float inv = 1.f / s;
    bool used[NE];
    for (int e = 0; e < NE; e++) used[e] = false;
    for (int kk = 0; kk < TOPK; kk++) {
        int best = -1; float bv = -1e30f;
        for (int e = 0; e < NE; e++)
            if (!used[e] && p[e] > bv) { bv = p[e]; best = e; }
        used[best] = true;
        te[t * TOPK + kk] = best;
        tw[t * TOPK + kk] = p[best] * inv;
    }
}

__global__ void count_kernel(const int* __restrict__ te, int* __restrict__ counts) {
    int p = blockIdx.x * 256 + threadIdx.x;
    if (p < NPAIR) atomicAdd(&counts[te[p]], 1);
}

__global__ void scan_kernel(const int* __restrict__ counts, int* __restrict__ offsets) {
    if (threadIdx.x == 0) {
        int s = 0;
        for (int e = 0; e < NE; e++) { offsets[e] = s; s += counts[e]; }
    }
}

__global__ void assign_kernel(const int* __restrict__ te, const int* __restrict__ offsets,
                              int* __restrict__ cursor, int* __restrict__ btok,
                              int* __restrict__ ppos) {
    int p = blockIdx.x * 256 + threadIdx.x;
    if (p >= NPAIR) return;
    int e = te[p];
    int pos = offsets[e] + atomicAdd(&cursor[e], 1);
    btok[pos] = p >> 3;
    ppos[p] = pos;
}

__global__ void silu_kernel(const float* __restrict__ gu, float* __restrict__ act) {
    long long idx = (long long)blockIdx.x * 256 + threadIdx.x;
    if (idx >= (long long)NPAIR * IDIM) return;
    long long p = idx / IDIM, f = idx % IDIM;
    float g = gu[p * (2 * IDIM) + f];
    float u = gu[p * (2 * IDIM) + IDIM + f];
    act[idx] = (g / (1.f + expf(-g))) * u;
}

__global__ void combine_kernel(const float* __restrict__ h, const float* __restrict__ ybuf,
                               const int* __restrict__ ppos, const float* __restrict__ tw,
                               float* __restrict__ out) {
    int t = blockIdx.x;
    __shared__ int   pos[TOPK];
    __shared__ float ww[TOPK];
    if (threadIdx.x < TOPK) {
        pos[threadIdx.x] = ppos[t * TOPK + threadIdx.x];
        ww[threadIdx.x]  = tw[t * TOPK + threadIdx.x];
    }
    __syncthreads();
    for (int c = threadIdx.x; c < HDM; c += 256) {
        float acc = h[(long long)t * HDM + c];
        #pragma unroll
        for (int kk = 0; kk < TOPK; kk++)
            acc += ww[kk] * ybuf[(long long)pos[kk] * HDM + c];
        out[(long long)t * HDM + c] = acc;
    }
}

// ---------------- exact fp32 SIMT GEMM (gate logits only) ----------------
__global__ void gemm_simt_kernel(const float* __restrict__ A, const float* __restrict__ B,
                                 float* __restrict__ C, int M, int N, int K,
                                 int lda, int ldb, int ldc) {
    __shared__ float As[16][64 + 4];
    __shared__ float Bs[16][64];
    int tid = threadIdx.x;
    int tx = tid & 15, ty = tid >> 4;
    int row0 = blockIdx.y * 64;
    int col0 = blockIdx.x * 64;
    float acc[4][4] = {};
    for (int k0 = 0; k0 < K; k0 += 16) {
        for (int i = tid; i < 64 * 16; i += 256) {
            int m = i >> 4, kk = i & 15;
            int gr = row0 + m;
            As[kk][m] = (gr < M) ? A[(long long)gr * lda + k0 + kk] : 0.f;
        }
        for (int i = tid; i < 16 * 64; i += 256) {
            int kk = i >> 6, n = i & 63;
            int gc = col0 + n;
            Bs[kk][n] = (gc < N) ? B[(long long)(k0 + kk) * ldb + gc] : 0.f;
        }
        __syncthreads();
        #pragma unroll
        for (int kk = 0; kk < 16; kk++) {
            float a[4], b[4];
            #pragma unroll
            for (int i = 0; i < 4; i++) a[i] = As[kk][ty * 4 + i];
            #pragma unroll
            for (int j = 0; j < 4; j++) b[j] = Bs[kk][tx * 4 + j];
            #pragma unroll
            for (int i = 0; i < 4; i++)
                #pragma unroll
                for (int j = 0; j < 4; j++)
                    acc[i][j] += a[i] * b[j];
        }
        __syncthreads();
    }
    #pragma unroll
    for (int i = 0; i < 4; i++) {
        int r = row0 + ty * 4 + i;
        if (r >= M) continue;
        #pragma unroll
        for (int j = 0; j < 4; j++) {
            int c = col0 + tx * 4 + j;
            if (c < N) C[(long long)r * ldc + c] = acc[i][j];
        }
    }
}

// ---------------- tf32 tensor-core GEMM, cp.async double-buffered ----------------
// modes: 0 = batched; 1 = gathered rows via btok; 2 = contiguous rows from offsets
template<int BM, int BN, int TRANSB>
__global__ void __launch_bounds__(256, 1)
gemm_tc(const float* __restrict__ A, const float* __restrict__ B, float* __restrict__ C,
        const float* __restrict__ resid,
        int M, int N, int K, int lda, int ldb, int ldc,
        long long sA, long long sB, long long sC, int bDivB,
        int causal, int trimK, float alpha, int mode,
        const int* __restrict__ counts, const int* __restrict__ offsets,
        const int* __restrict__ btok) {
    constexpr int WM = BM / 2, WN = BN / 4;
    constexpr int FM = WM / 16, FN = WN / 8;
    constexpr int BROWS = TRANSB ? BN : 16;
    constexpr int BCOLS = TRANSB ? 20 : BN + 8;

    int z = blockIdx.z;
    const float* Az = (mode == 0) ? (A + (long long)z * sA) : A;
    const float* Bz = (mode == 0) ? (B + (long long)(z / bDivB) * sB)
                                  : (B + (long long)z * sB);
    float* Cz = (mode == 0) ? (C + (long long)z * sC) : C;

    int cnt = M, start = 0;
    if (mode) { cnt = counts[z]; start = offsets[z]; }

    int row0 = blockIdx.y * BM, col0 = blockIdx.x * BN;
    if (mode && row0 >= cnt) return;
    if (causal && col0 > row0) return;

    __shared__ float As[2][BM][20];
    __shared__ float Bs[2][BROWS][BCOLS];
    __shared__ int stok[BM];

    int tid = threadIdx.x;
    if (mode == 1) {
        for (int i = tid; i < BM; i += 256)
            stok[i] = (row0 + i < cnt) ? btok[start + row0 + i] : 0;
        __syncthreads();
    }

    int warp = tid >> 5, lane = tid & 31;
    int wr = (warp >> 2) * WM, wc = (warp & 3) * WN;
    int g = lane >> 2, t = lane & 3;

    float acc[FM][FN][4];
    #pragma unroll
    for (int i = 0; i < FM; i++)
        #pragma unroll
        for (int j = 0; j < FN; j++)
            #pragma unroll
            for (int r = 0; r < 4; r++) acc[i][j][r] = 0.f;

    auto loadTiles = [&](int st, int k0) {
        // A: BM rows x 16 k, 4 chunks of 16B per row
        #pragma unroll
        for (int i = tid; i < BM * 4; i += 256) {
            int r = i >> 2, kq = i & 3;
            bool val = (row0 + r < cnt);
            long long ar = 0;
            if (val) {
                if (mode == 1)      ar = stok[r];
                else if (mode == 2) ar = start + row0 + r;
                else                ar = row0 + r;
            }
            cpasync16(&As[st][r][kq * 4], Az + ar * lda + k0 + kq * 4, val ? 16 : 0);
        }
        if (!TRANSB) {
            #pragma unroll
            for (int i = tid; i < 16 * (BN / 4); i += 256) {
                int kk = i / (BN / 4), nq = i % (BN / 4);
                cpasync16(&Bs[st][kk][nq * 4],
                          Bz + (long long)(k0 + kk) * ldb + col0 + nq * 4, 16);
            }
        } else {
            #pragma unroll
            for (int i = tid; i < BN * 4; i += 256) {
                int n = i >> 2, kq = i & 3;
                cpasync16(&Bs[st][n][kq * 4],
                          Bz + (long long)(col0 + n) * ldb + k0 + kq * 4, 16);
            }
        }
        cpasync_commit();
    };

    auto compute = [&](int st) {
        #pragma unroll
        for (int ks = 0; ks < 2; ks++) {
            int kb = ks * 8;
            uint32_t a[FM][4], b[FN][2];
            #pragma unroll
            for (int fm = 0; fm < FM; fm++) {
                int m0 = wr + fm * 16;
                a[fm][0] = __float_as_uint(As[st][m0 + g][kb + t]);
                a[fm][1] = __float_as_uint(As[st][m0 + g + 8][kb + t]);
                a[fm][2] = __float_as_uint(As[st][m0 + g][kb + t + 4]);
                a[fm][3] = __float_as_uint(As[st][m0 + g + 8][kb + t + 4]);
            }
            #pragma unroll
            for (int fn = 0; fn < FN; fn++) {
                int n0 = wc + fn * 8 + g;
                if (TRANSB) {
                    b[fn][0] = __float_as_uint(Bs[st][n0][kb + t]);
                    b[fn][1] = __float_as_uint(Bs[st][n0][kb + t + 4]);
                } else {
                    b[fn][0] = __float_as_uint(Bs[st][kb + t][n0]);
                    b[fn][1] = __float_as_uint(Bs[st][kb + t + 4][n0]);
                }
            }
            #pragma unroll
            for (int fm = 0; fm < FM; fm++)
                #pragma unroll
                for (int fn = 0; fn < FN; fn++) {
                    asm volatile(
                        "mma.sync.aligned.m16n8k8.row.col.f32.tf32.tf32.f32 "
                        "{%0,%1,%2,%3}, {%4,%5,%6,%7}, {%8,%9}, {%0,%1,%2,%3};"
                        : "+f"(acc[fm][fn][0]), "+f"(acc[fm][fn][1]),
                          "+f"(acc[fm][fn][2]), "+f"(acc[fm][fn][3])
                        : "r"(a[fm][0]), "r"(a[fm][1]), "r"(a[fm][2]), "r"(a[fm][3]),
                          "r"(b[fn][0]), "r"(b[fn][1]));
                }
        }
    };

    int kLimit = trimK ? (row0 + BM < K ? row0 + BM : K) : K;
    int nk = kLimit >> 4;

    loadTiles(0, 0);
    for (int ks = 0; ks < nk; ks++) {
        int cur = ks & 1;
        if (ks + 1 < nk) {
            loadTiles(cur ^ 1, (ks + 1) << 4);
            asm volatile("cp.async.wait_group 1;" ::: "memory");
        } else {
            asm volatile("cp.async.wait_group 0;" ::: "memory");
        }
        __syncthreads();
        compute(cur);
        __syncthreads();
    }

    // ---- epilogue ----
    #pragma unroll
    for (int fm = 0; fm < FM; fm++) {
        #pragma unroll
        for (int rr = 0; rr < 2; rr++) {
            int lr = wr + fm * 16 + g + rr * 8;
            if (row0 + lr >= cnt) continue;
            long long crow = (mode == 0) ? (long long)(row0 + lr)
                                         : (long long)(start + row0 + lr);
            float* cp = Cz + crow * ldc;
            const float* rp = resid ? (resid + (long long)(row0 + lr) * ldc) : nullptr;
            #pragma unroll
            for (int fn = 0; fn < FN; fn++) {
                int c = col0 + wc + fn * 8 + t * 2;
                float v0 = alpha * acc[fm][fn][rr * 2 + 0];
                float v1 = alpha * acc[fm][fn][rr * 2 + 1];
                if (rp) { v0 += rp[c]; v1 += rp[c + 1]; }
                cp[c] = v0;
                cp[c + 1] = v1;
            }
        }
    }
}

// ---------------- host launcher ----------------
static void* symaddr(const void* s) { void* p = nullptr; cudaGetSymbolAddress(&p, s); return p; }

extern "C" void kernel_launch(void* const* d_in, const int* in_sizes, int n_in,
                              void* d_out, int out_size) {
    const float* x   = (const float*)d_in[0];
    const float* ln1 = (const float*)d_in[1];
    const float* ln2 = (const float*)d_in[2];
    const float* qnw = (const float*)d_in[3];
    const float* knw = (const float*)d_in[4];
    const float* Wq  = (const float*)d_in[5];
    const float* Wk  = (const float*)d_in[6];
    const float* Wv  = (const float*)d_in[7];
    const float* Wo  = (const float*)d_in[8];
    const float* Wg  = (const float*)d_in[9];
    const float* Wgu = (const float*)d_in[10];
    const float* Wd  = (const float*)d_in[11];
    float* out = (float*)d_out;

    float* h1   = (float*)symaddr(g_h1);
    float* q    = (float*)symaddr(g_q);
    float* k    = (float*)symaddr(g_k);
    float* v    = (float*)symaddr(g_v);
    float* sc   = (float*)symaddr(g_scores);
    float* attn = (float*)symaddr(g_attn);
    float* h    = (float*)symaddr(g_h);
    float* h2   = (float*)symaddr(g_h2);
    float* lg   = (float*)symaddr(g_logits);
    float* tw   = (float*)symaddr(g_tw);
    int*   te   = (int*)symaddr(g_te);
    int*   cnts = (int*)symaddr(g_counts);
    int*   offs = (int*)symaddr(g_offsets);
    int*   cur  = (int*)symaddr(g_cursor);
    int*   btok = (int*)symaddr(g_btok);
    int*   ppos = (int*)symaddr(g_ppos);
    float* gu   = (float*)symaddr(g_gu);
    float* act  = (float*)symaddr(g_act);
    float* ybuf = (float*)symaddr(g_ybuf);

    const float scale = 0.08838834764831843f;   // 1/sqrt(128)

    zero32_kernel<<<1, 32>>>(cnts, cur);

    // ---- attention ----
    rmsnorm_kernel<<<SQ, 256>>>(x, ln1, h1, HDM);

    gemm_tc<128,128,0><<<dim3(32, 8, 1), 256>>>(h1, Wq, q, nullptr,
        SQ, NHQ*HDHD, HDM, HDM, NHQ*HDHD, NHQ*HDHD,
        0, 0, 0, 1, 0, 0, 1.f, 0, nullptr, nullptr, nullptr);
    gemm_tc<64,64,0><<<dim3(8, 16, 1), 256>>>(h1, Wk, k, nullptr,
        SQ, NKVH*HDHD, HDM, HDM, NKVH*HDHD, NKVH*HDHD,
        0, 0, 0, 1, 0, 0, 1.f, 0, nullptr, nullptr, nullptr);
    gemm_tc<64,64,0><<<dim3(8, 16, 1), 256>>>(h1, Wv, v, nullptr,
        SQ, NKVH*HDHD, HDM, HDM, NKVH*HDHD, NKVH*HDHD,
        0, 0, 0, 1, 0, 0, 1.f, 0, nullptr, nullptr, nullptr);

    qknorm_rope_kernel<<<dim3(NHQ + NKVH, SQ), 128>>>(q, k, qnw, knw);

    // scores = q @ k^T (causal block-skip)
    gemm_tc<128,128,1><<<dim3(8, 8, NHQ), 256>>>(q, k, sc, nullptr,
        SQ, SQ, HDHD, NHQ*HDHD, NKVH*HDHD, SQ,
        HDHD, HDHD, (long long)SQ*SQ, 8, 1, 0, scale, 0, nullptr, nullptr, nullptr);

    softmax_kernel<<<dim3(SQ, NHQ), 256>>>(sc);

    // attn = probs @ v (K-loop trimmed at diagonal)
    gemm_tc<128,128,0><<<dim3(1, 8, NHQ), 256>>>(sc, v, attn, nullptr,
        SQ, HDHD, SQ, SQ, NKVH*HDHD, NHQ*HDHD,
        (long long)SQ*SQ, HDHD, HDHD, 8, 0, 1, 1.f, 0, nullptr, nullptr, nullptr);

    // h = x + attn @ Wo
    gemm_tc<128,128,0><<<dim3(16, 8, 1), 256>>>(attn, Wo, h, x,
        SQ, HDM, NHQ*HDHD, NHQ*HDHD, HDM, HDM,
        0, 0, 0, 1, 0, 0, 1.f, 0, nullptr, nullptr, nullptr);

    // ---- MoE ----
    rmsnorm_kernel<<<SQ, 256>>>(h, ln2, h2, HDM);

    gemm_simt_kernel<<<dim3(1, 16, 1), 256>>>(h2, Wg, lg, SQ, NE, HDM, HDM, NE, NE);
    topk_kernel<<<4, 256>>>(lg, tw, te);
    count_kernel<<<(NPAIR + 255) / 256, 256>>>(te, cnts);
    scan_kernel<<<1, 32>>>(cnts, offs);
    assign_kernel<<<(NPAIR + 255) / 256, 256>>>(te, offs, cur, btok, ppos);

    gemm_tc<128,128,0><<<dim3(2*IDIM/128, 8, NE), 256>>>(h2, Wgu, gu, nullptr,
        SQ, 2*IDIM, HDM, HDM, 2*IDIM, 2*IDIM,
        0, (long long)HDM*2*IDIM, 0, 1, 0, 0, 1.f, 1, cnts, offs, btok);

    silu_kernel<<<(int)(((long long)NPAIR*IDIM + 255) / 256), 256>>>(gu, act);

    gemm_tc<128,128,0><<<dim3(HDM/128, 8, NE), 256>>>(act, Wd, ybuf, nullptr,
        SQ, HDM, IDIM, IDIM, HDM, HDM,
        0, (long long)IDIM*HDM, 0, 1, 0, 0, 1.f, 2, cnts, offs, nullptr);

    combine_kernel<<<SQ, 256>>>(h, ybuf, ppos, tw, out);
}

// round 4
// speedup vs baseline: 4.0736x; 1.0893x over previous
#include <cuda_runtime.h>
#include <math.h>
#include <stdint.h>

// ---------------- problem constants ----------------
#define SQ   1024
#define HDM  2048
#define NHQ  32
#define NKVH 4
#define HDHD 128
#define NE   32
#define TOPK 8
#define IDIM 768
#define NPAIR (SQ*TOPK)   // 8192

// ---------------- device scratch ----------------
__device__ float g_h1[SQ*HDM];
__device__ float g_q [SQ*NHQ*HDHD];
__device__ float g_k [SQ*NKVH*HDHD];
__device__ float g_v [SQ*NKVH*HDHD];
__device__ float g_scores[(long long)NHQ*SQ*SQ];
__device__ float g_attn[SQ*NHQ*HDHD];
__device__ float g_h [SQ*HDM];
__device__ float g_h2[SQ*HDM];
__device__ float g_logits[SQ*NE];
__device__ float g_tw[NPAIR];
__device__ int   g_te[NPAIR];
__device__ int   g_counts[NE];
__device__ int   g_offsets[NE];
__device__ int   g_cursor[NE];
__device__ int   g_btok[NPAIR];
__device__ int   g_ppos[NPAIR];
__device__ float g_gu [(long long)NPAIR*2*IDIM];
__device__ float g_act[(long long)NPAIR*IDIM];
__device__ float g_ybuf[(long long)NPAIR*HDM];

// ---------------- helpers ----------------
__device__ __forceinline__ void cpasync16(void* dst, const void* src, int srcsize) {
    uint32_t d = (uint32_t)__cvta_generic_to_shared(dst);
    asm volatile("cp.async.cg.shared.global [%0], [%1], 16, %2;"
                 :: "r"(d), "l"(src), "r"(srcsize) : "memory");
}
__device__ __forceinline__ void cpasync_commit() {
    asm volatile("cp.async.commit_group;" ::: "memory");
}
// round-to-nearest-away into tf32's 19 kept bits (mma ignores low 13 bits)
__device__ __forceinline__ uint32_t rnd(float v) {
    return __float_as_uint(v) + 0x1000u;
}

// ---------------- small kernels ----------------
__global__ void zero32_kernel(int* counts, int* cursor) {
    int i = threadIdx.x;
    if (i < NE) { counts[i] = 0; cursor[i] = 0; }
}

__global__ void rmsnorm_kernel(const float* __restrict__ x, const float* __restrict__ w,
                               float* __restrict__ o, int ncols) {
    int row = blockIdx.x;
    const float* xr = x + (long long)row * ncols;
    float* orow = o + (long long)row * ncols;
    __shared__ float red[256];
    float s = 0.f;
    for (int c = threadIdx.x; c < ncols; c += 256) { float t = xr[c]; s += t * t; }
    red[threadIdx.x] = s; __syncthreads();
    for (int st = 128; st > 0; st >>= 1) {
        if (threadIdx.x < st) red[threadIdx.x] += red[threadIdx.x + st];
        __syncthreads();
    }
    float rms = rsqrtf(red[0] / (float)ncols + 1e-6f);
    for (int c = threadIdx.x; c < ncols; c += 256) orow[c] = xr[c] * rms * w[c];
}

__global__ void qknorm_rope_kernel(float* __restrict__ q, float* __restrict__ k,
                                   const float* __restrict__ qw, const float* __restrict__ kw) {
    int slot = blockIdx.x;
    int t    = blockIdx.y;
    float* vec; const float* w;
    if (slot < NHQ) { vec = q + (long long)t * (NHQ*HDHD) + slot * HDHD; w = qw; }
    else            { vec = k + (long long)t * (NKVH*HDHD) + (slot - NHQ) * HDHD; w = kw; }
    int d = threadIdx.x;
    float v = vec[d];
    float s = v * v;
    #pragma unroll
    for (int o = 16; o > 0; o >>= 1) s += __shfl_xor_sync(0xffffffffu, s, o);
    __shared__ float red[4];
    if ((d & 31) == 0) red[d >> 5] = s;
    __syncthreads();
    float tot = red[0] + red[1] + red[2] + red[3];
    float rms = rsqrtf(tot / 128.f + 1e-6f);
    float nv = v * rms * w[d];
    __shared__ float sv[128];
    sv[d] = nv;
    __syncthreads();
    int d2 = d & 63;
    float angle = (float)t * powf(10000.0f, -(float)(2 * d2) / 128.0f);
    float c = cosf(angle), sn = sinf(angle);
    float other = (d < 64) ? -sv[d + 64] : sv[d - 64];
    vec[d] = nv * c + other * sn;
}

__global__ void softmax_kernel(float* __restrict__ scores) {
    int i = blockIdx.x, h = blockIdx.y;
    float* row = scores + ((long long)h * SQ + i) * SQ;
    int len = i + 1;
    __shared__ float red[256];
    float m = -1e30f;
    for (int j = threadIdx.x; j < len; j += 256) m = fmaxf(m, row[j]);
    red[threadIdx.x] = m; __syncthreads();
    for (int st = 128; st > 0; st >>= 1) {
        if (threadIdx.x < st) red[threadIdx.x] = fmaxf(red[threadIdx.x], red[threadIdx.x + st]);
        __syncthreads();
    }
    m = red[0]; __syncthreads();
    float s = 0.f;
    for (int j = threadIdx.x; j < len; j += 256) { float e = expf(row[j] - m); row[j] = e; s += e; }
    red[threadIdx.x] = s; __syncthreads();
    for (int st = 128; st > 0; st >>= 1) {
        if (threadIdx.x < st) red[threadIdx.x] += red[threadIdx.x + st];
        __syncthreads();
    }
    float inv = 1.f / red[0];
    int fill = ((i >> 7) + 1) << 7;   // AV K-loop trims at 128-block boundary
    for (int j = threadIdx.x; j < fill; j += 256) row[j] = (j < len) ? row[j] * inv : 0.f;
}

__global__ void topk_kernel(const float* __restrict__ logits, float* __restrict__ tw,
                            int* __restrict__ te) {
    int t = blockIdx.x * blockDim.x + threadIdx.x;
    if (t >= SQ) return;
    float p[NE];
    float m = -1e30f;
    for (int e = 0; e < NE; e++) { p[e] = logits[t * NE + e]; m = fmaxf(m, p[e]); }
    float s = 0.f;
    for (int e = 0; e < NE; e++) { p[e] = expf(p[e] - m); s += p[e]; }
    float inv = 1.f / s;
    bool used[NE];
    for (int e = 0; e < NE; e++) used[e] = false;
    for (int kk = 0; kk < TOPK; kk++) {
        int best = -1; float bv = -1e30f;
        for (int e = 0; e < NE; e++)
            if (!used[e] && p[e] > bv) { bv = p[e]; best = e; }
        used[best] = true;
        te[t * TOPK + kk] = best;
        tw[t * TOPK + kk] = p[best] * inv;
    }
}

__global__ void count_kernel(const int* __restrict__ te, int* __restrict__ counts) {
    int p = blockIdx.x * 256 + threadIdx.x;
    if (p < NPAIR) atomicAdd(&counts[te[p]], 1);
}

__global__ void scan_kernel(const int* __restrict__ counts, int* __restrict__ offsets) {
    if (threadIdx.x == 0) {
        int s = 0;
        for (int e = 0; e < NE; e++) { offsets[e] = s; s += counts[e]; }
    }
}

__global__ void assign_kernel(const int* __restrict__ te, const int* __restrict__ offsets,
                              int* __restrict__ cursor, int* __restrict__ btok,
                              int* __restrict__ ppos) {
    int p = blockIdx.x * 256 + threadIdx.x;
    if (p >= NPAIR) return;
    int e = te[p];
    int pos = offsets[e] + atomicAdd(&cursor[e], 1);
    btok[pos] = p >> 3;
    ppos[p] = pos;
}

__global__ void silu_kernel(const float* __restrict__ gu, float* __restrict__ act) {
    long long idx = (long long)blockIdx.x * 256 + threadIdx.x;
    if (idx >= (long long)NPAIR * IDIM) return;
    long long p = idx / IDIM, f = idx % IDIM;
    float g = gu[p * (2 * IDIM) + f];
    float u = gu[p * (2 * IDIM) + IDIM + f];
    act[idx] = (g / (1.f + expf(-g))) * u;
}

__global__ void combine_kernel(const float* __restrict__ h, const float* __restrict__ ybuf,
                               const int* __restrict__ ppos, const float* __restrict__ tw,
                               float* __restrict__ out) {
    int t = blockIdx.x;
    __shared__ int   pos[TOPK];
    __shared__ float ww[TOPK];
    if (threadIdx.x < TOPK) {
        pos[threadIdx.x] = ppos[t * TOPK + threadIdx.x];
        ww[threadIdx.x]  = tw[t * TOPK + threadIdx.x];
    }
    __syncthreads();
    for (int c = threadIdx.x; c < HDM; c += 256) {
        float acc = h[(long long)t * HDM + c];
        #pragma unroll
        for (int kk = 0; kk < TOPK; kk++)
            acc += ww[kk] * ybuf[(long long)pos[kk] * HDM + c];
        out[(long long)t * HDM + c] = acc;
    }
}

// ---------------- exact fp32 SIMT GEMM (gate logits only) ----------------
__global__ void gemm_simt_kernel(const float* __restrict__ A, const float* __restrict__ B,
                                 float* __restrict__ C, int M, int N, int K,
                                 int lda, int ldb, int ldc) {
    __shared__ float As[16][64 + 4];
    __shared__ float Bs[16][64];
    int tid = threadIdx.x;
    int tx = tid & 15, ty = tid >> 4;
    int row0 = blockIdx.y * 64;
    int col0 = blockIdx.x * 64;
    float acc[4][4] = {};
    for (int k0 = 0; k0 < K; k0 += 16) {
        for (int i = tid; i < 64 * 16; i += 256) {
            int m = i >> 4, kk = i & 15;
            int gr = row0 + m;
            As[kk][m] = (gr < M) ? A[(long long)gr * lda + k0 + kk] : 0.f;
        }
        for (int i = tid; i < 16 * 64; i += 256) {
            int kk = i >> 6, n = i & 63;
            int gc = col0 + n;
            Bs[kk][n] = (gc < N) ? B[(long long)(k0 + kk) * ldb + gc] : 0.f;
        }
        __syncthreads();
        #pragma unroll
        for (int kk = 0; kk < 16; kk++) {
            float a[4], b[4];
            #pragma unroll
            for (int i = 0; i < 4; i++) a[i] = As[kk][ty * 4 + i];
            #pragma unroll
            for (int j = 0; j < 4; j++) b[j] = Bs[kk][tx * 4 + j];
            #pragma unroll
            for (int i = 0; i < 4; i++)
                #pragma unroll
                for (int j = 0; j < 4; j++)
                    acc[i][j] += a[i] * b[j];
        }
        __syncthreads();
    }
    #pragma unroll
    for (int i = 0; i < 4; i++) {
        int r = row0 + ty * 4 + i;
        if (r >= M) continue;
        #pragma unroll
        for (int j = 0; j < 4; j++) {
            int c = col0 + tx * 4 + j;
            if (c < N) C[(long long)r * ldc + c] = acc[i][j];
        }
    }
}

// ---------------- tf32 tensor-core GEMM, BK=32, 3-stage cp.async ----------------
// modes: 0 = batched; 1 = gathered rows via btok; 2 = contiguous rows from offsets;
//        3 = fused QKV (B/C = Wq/q, B2/C2 = Wk/k, B3/C3 = Wv/v)
#define BK 32
#define ASTRIDE 36
#define ASZ (128*ASTRIDE)                 // floats per A stage
template<int TRANSB>
__global__ void __launch_bounds__(256, 1)
gemm_tc(const float* __restrict__ A, const float* __restrict__ B, float* __restrict__ C,
        const float* __restrict__ resid,
        int M, int K, int lda, int ldb, int ldc,
        long long sA, long long sB, long long sC, int bDivB,
        int causal, int trimK, float alpha, int mode,
        const int* __restrict__ counts, const int* __restrict__ offsets,
        const int* __restrict__ btok,
        const float* __restrict__ B2, float* __restrict__ C2,
        const float* __restrict__ B3, float* __restrict__ C3) {
    constexpr int BM = 128, BN = 128;
    constexpr int WM = 64, WN = 32;
    constexpr int FM = 4, FN = 4;
    constexpr int BSZ = TRANSB ? (BN * ASTRIDE) : (BK * (BN + 8));

    extern __shared__ float smem[];
    float* sA_ = smem;                 // 3 stages of A
    float* sB_ = smem + 3 * ASZ;       // 3 stages of B
    __shared__ int stok[BM];

    int z = blockIdx.z;
    int tid = threadIdx.x;
    int row0 = blockIdx.y * BM;
    int col0 = blockIdx.x * BN;

    const float* Az = A;
    const float* Bz;
    float* Cz;
    if (mode == 0) {
        Az = A + (long long)z * sA;
        Bz = B + (long long)(z / bDivB) * sB;
        Cz = C + (long long)z * sC;
    } else if (mode == 3) {
        if (z < 32)      { Bz = B;  Cz = C;  ldb = ldc = NHQ*HDHD;  col0 = z * BN; }
        else if (z < 36) { Bz = B2; Cz = C2; ldb = ldc = NKVH*HDHD; col0 = (z - 32) * BN; }
        else             { Bz = B3; Cz = C3; ldb = ldc = NKVH*HDHD; col0 = (z - 36) * BN; }
    } else {
        Bz = B + (long long)z * sB;
        Cz = C;
    }

    int cnt = M, start = 0;
    if (mode == 1 || mode == 2) { cnt = counts[z]; start = offsets[z]; }
    if ((mode == 1 || mode == 2) && row0 >= cnt) return;
    if (causal && col0 > row0) return;

    if (mode == 1) {
        for (int i = tid; i < BM; i += 256)
            stok[i] = (row0 + i < cnt) ? btok[start + row0 + i] : 0;
        __syncthreads();
    }

    int warp = tid >> 5, lane = tid & 31;
    int wr = (warp >> 2) * WM, wc = (warp & 3) * WN;
    int g = lane >> 2, t = lane & 3;

    float acc[FM][FN][4];
    #pragma unroll
    for (int i = 0; i < FM; i++)
        #pragma unroll
        for (int j = 0; j < FN; j++)
            #pragma unroll
            for (int r = 0; r < 4; r++) acc[i][j][r] = 0.f;

    auto loadTiles = [&](int st, int k0) {
        float* a = sA_ + st * ASZ;
        float* b = sB_ + st * BSZ;
        #pragma unroll
        for (int i = tid; i < BM * 8; i += 256) {
            int r = i >> 3, kq = i & 7;
            bool val = (row0 + r < cnt);
            long long ar = 0;
            if (val) {
                if (mode == 1)      ar = stok[r];
                else if (mode == 2) ar = start + row0 + r;
                else                ar = row0 + r;
            }
            cpasync16(a + r * ASTRIDE + kq * 4, Az + ar * lda + k0 + kq * 4, val ? 16 : 0);
        }
        if (!TRANSB) {
            #pragma unroll
            for (int i = tid; i < BK * (BN / 4); i += 256) {
                int kk = i >> 5, nq = i & 31;
                cpasync16(b + kk * (BN + 8) + nq * 4,
                          Bz + (long long)(k0 + kk) * ldb + col0 + nq * 4, 16);
            }
        } else {
            #pragma unroll
            for (int i = tid; i < BN * 8; i += 256) {
                int n = i >> 3, kq = i & 7;
                cpasync16(b + n * ASTRIDE + kq * 4,
                          Bz + (long long)(col0 + n) * ldb + k0 + kq * 4, 16);
            }
        }
    };

    auto compute = [&](int st) {
        const float* a_ = sA_ + st * ASZ;
        const float* b_ = sB_ + st * BSZ;
        #pragma unroll
        for (int ks = 0; ks < 4; ks++) {
            int kb = ks * 8;
            uint32_t a[FM][4], b[FN][2];
            #pragma unroll
            for (int fm = 0; fm < FM; fm++) {
                int m0 = wr + fm * 16;
                a[fm][0] = rnd(a_[(m0 + g) * ASTRIDE + kb + t]);
                a[fm][1] = rnd(a_[(m0 + g + 8) * ASTRIDE + kb + t]);
                a[fm][2] = rnd(a_[(m0 + g) * ASTRIDE + kb + t + 4]);
                a[fm][3] = rnd(a_[(m0 + g + 8) * ASTRIDE + kb + t + 4]);
            }
            #pragma unroll
            for (int fn = 0; fn < FN; fn++) {
                int n0 = wc + fn * 8 + g;
                if (TRANSB) {
                    b[fn][0] = rnd(b_[n0 * ASTRIDE + kb + t]);
                    b[fn][1] = rnd(b_[n0 * ASTRIDE + kb + t + 4]);
                } else {
                    b[fn][0] = rnd(b_[(kb + t) * (BN + 8) + n0]);
                    b[fn][1] = rnd(b_[(kb + t + 4) * (BN + 8) + n0]);
                }
            }
            #pragma unroll
            for (int fm = 0; fm < FM; fm++)
                #pragma unroll
                for (int fn = 0; fn < FN; fn++) {
                    asm volatile(
                        "mma.sync.aligned.m16n8k8.row.col.f32.tf32.tf32.f32 "
                        "{%0,%1,%2,%3}, {%4,%5,%6,%7}, {%8,%9}, {%0,%1,%2,%3};"
                        : "+f"(acc[fm][fn][0]), "+f"(acc[fm][fn][1]),
                          "+f"(acc[fm][fn][2]), "+f"(acc[fm][fn][3])
                        : "r"(a[fm][0]), "r"(a[fm][1]), "r"(a[fm][2]), "r"(a[fm][3]),
                          "r"(b[fn][0]), "r"(b[fn][1]));
                }
        }
    };

    int kLimit = trimK ? (row0 + BM < K ? row0 + BM : K) : K;
    int nk = kLimit / BK;

    loadTiles(0, 0);      cpasync_commit();
    loadTiles(1, BK);     cpasync_commit();
    for (int ks = 0; ks < nk; ks++) {
        asm volatile("cp.async.wait_group 1;" ::: "memory");
        __syncthreads();
        if (ks + 2 < nk) loadTiles((ks + 2) % 3, (ks + 2) * BK);
        cpasync_commit();
        compute(ks % 3);
    }

    // ---- epilogue ----
    #pragma unroll
    for (int fm = 0; fm < FM; fm++) {
        #pragma unroll
        for (int rr = 0; rr < 2; rr++) {
            int lr = wr + fm * 16 + g + rr * 8;
            if (row0 + lr >= cnt) continue;
            long long crow = (mode == 1 || mode == 2) ? (long long)(start + row0 + lr)
                                                      : (long long)(row0 + lr);
            float* cp = Cz + crow * ldc;
            const float* rp = resid ? (resid + (long long)(row0 + lr) * ldc) : nullptr;
            #pragma unroll
            for (int fn = 0; fn < FN; fn++) {
                int c = col0 + wc + fn * 8 + t * 2;
                float v0 = alpha * acc[fm][fn][rr * 2 + 0];
                float v1 = alpha * acc[fm][fn][rr * 2 + 1];
                if (rp) { v0 += rp[c]; v1 += rp[c + 1]; }
                cp[c] = v0;
                cp[c + 1] = v1;
            }
        }
    }
}

// ---------------- host launcher ----------------
static void* symaddr(const void* s) { void* p = nullptr; cudaGetSymbolAddress(&p, s); return p; }

extern "C" void kernel_launch(void* const* d_in, const int* in_sizes, int n_in,
                              void* d_out, int out_size) {
    const float* x   = (const float*)d_in[0];
    const float* ln1 = (const float*)d_in[1];
    const float* ln2 = (const float*)d_in[2];
    const float* qnw = (const float*)d_in[3];
    const float* knw = (const float*)d_in[4];
    const float* Wq  = (const float*)d_in[5];
    const float* Wk  = (const float*)d_in[6];
    const float* Wv  = (const float*)d_in[7];
    const float* Wo  = (const float*)d_in[8];
    const float* Wg  = (const float*)d_in[9];
    const float* Wgu = (const float*)d_in[10];
    const float* Wd  = (const float*)d_in[11];
    float* out = (float*)d_out;

    float* h1   = (float*)symaddr(g_h1);
    float* q    = (float*)symaddr(g_q);
    float* k    = (float*)symaddr(g_k);
    float* v    = (float*)symaddr(g_v);
    float* sc   = (float*)symaddr(g_scores);
    float* attn = (float*)symaddr(g_attn);
    float* h    = (float*)symaddr(g_h);
    float* h2   = (float*)symaddr(g_h2);
    float* lg   = (float*)symaddr(g_logits);
    float* tw   = (float*)symaddr(g_tw);
    int*   te   = (int*)symaddr(g_te);
    int*   cnts = (int*)symaddr(g_counts);
    int*   offs = (int*)symaddr(g_offsets);
    int*   cur  = (int*)symaddr(g_cursor);
    int*   btok = (int*)symaddr(g_btok);
    int*   ppos = (int*)symaddr(g_ppos);
    float* gu   = (float*)symaddr(g_gu);
    float* act  = (float*)symaddr(g_act);
    float* ybuf = (float*)symaddr(g_ybuf);

    const float scale = 0.08838834764831843f;   // 1/sqrt(128)

    const size_t smem0 = (size_t)(3 * ASZ + 3 * (BK * (128 + 8))) * 4;   // non-trans
    const size_t smem1 = (size_t)(3 * ASZ + 3 * (128 * ASTRIDE)) * 4;    // trans
    static int attrDone = 0;
    if (!attrDone) {
        cudaFuncSetAttribute((const void*)gemm_tc<0>,
                             cudaFuncAttributeMaxDynamicSharedMemorySize, 120 * 1024);
        cudaFuncSetAttribute((const void*)gemm_tc<1>,
                             cudaFuncAttributeMaxDynamicSharedMemorySize, 120 * 1024);
        attrDone = 1;
    }

    zero32_kernel<<<1, 32>>>(cnts, cur);

    // ---- attention ----
    rmsnorm_kernel<<<SQ, 256>>>(x, ln1, h1, HDM);

    // fused QKV projection
    gemm_tc<0><<<dim3(1, 8, 40), 256, smem0>>>(h1, Wq, q, nullptr,
        SQ, HDM, HDM, 0, 0, 0, 0, 0, 1, 0, 0, 1.f, 3,
        nullptr, nullptr, nullptr, Wk, k, Wv, v);

    qknorm_rope_kernel<<<dim3(NHQ + NKVH, SQ), 128>>>(q, k, qnw, knw);

    // scores = q @ k^T (causal skip)
    gemm_tc<1><<<dim3(8, 8, NHQ), 256, smem1>>>(q, k, sc, nullptr,
        SQ, HDHD, NHQ*HDHD, NKVH*HDHD, SQ,
        HDHD, HDHD, (long long)SQ*SQ, 8, 1, 0, scale, 0,
        nullptr, nullptr, nullptr, nullptr, nullptr, nullptr, nullptr);

    softmax_kernel<<<dim3(SQ, NHQ), 256>>>(sc);

    // attn = probs @ v (K trimmed at diagonal)
    gemm_tc<0><<<dim3(1, 8, NHQ), 256, smem0>>>(sc, v, attn, nullptr,
        SQ, SQ, SQ, NKVH*HDHD, NHQ*HDHD,
        (long long)SQ*SQ, HDHD, HDHD, 8, 0, 1, 1.f, 0,
        nullptr, nullptr, nullptr, nullptr, nullptr, nullptr, nullptr);

    // h = x + attn @ Wo
    gemm_tc<0><<<dim3(16, 8, 1), 256, smem0>>>(attn, Wo, h, x,
        SQ, NHQ*HDHD, NHQ*HDHD, HDM, HDM,
        0, 0, 0, 1, 0, 0, 1.f, 0,
        nullptr, nullptr, nullptr, nullptr, nullptr, nullptr, nullptr);

    // ---- MoE ----
    rmsnorm_kernel<<<SQ, 256>>>(h, ln2, h2, HDM);

    gemm_simt_kernel<<<dim3(1, 16, 1), 256>>>(h2, Wg, lg, SQ, NE, HDM, HDM, NE, NE);
    topk_kernel<<<4, 256>>>(lg, tw, te);
    count_kernel<<<(NPAIR + 255) / 256, 256>>>(te, cnts);
    scan_kernel<<<1, 32>>>(cnts, offs);
    assign_kernel<<<(NPAIR + 255) / 256, 256>>>(te, offs, cur, btok, ppos);

    gemm_tc<0><<<dim3(2*IDIM/128, 8, NE), 256, smem0>>>(h2, Wgu, gu, nullptr,
        SQ, HDM, HDM, 2*IDIM, 2*IDIM,
        0, (long long)HDM*2*IDIM, 0, 1, 0, 0, 1.f, 1,
        cnts, offs, btok, nullptr, nullptr, nullptr, nullptr);

    silu_kernel<<<(int)(((long long)NPAIR*IDIM + 255) / 256), 256>>>(gu, act);

    gemm_tc<0><<<dim3(HDM/128, 8, NE), 256, smem0>>>(act, Wd, ybuf, nullptr,
        SQ, IDIM, IDIM, HDM, HDM,
        0, (long long)IDIM*HDM, 0, 1, 0, 0, 1.f, 2,
        cnts, offs, nullptr, nullptr, nullptr, nullptr, nullptr);

    combine_kernel<<<SQ, 256>>>(h, ybuf, ppos, tw, out);
}